// round 1
// baseline (speedup 1.0000x reference)
#include <cuda_runtime.h>
#include <math.h>

// Problem constants
#define S_      8
#define U_      8
#define KSTEPS  12
#define NEG     17
#define ZD      64
#define CD      256
#define T_      1140
#define LEN     1128
#define SU      64              // S_*U_
#define MROWS   (SU*LEN)        // 72192
#define WC_PER_K ((size_t)MROWS*ZD)   // 4,620,288 floats per k

// Scratch (no cudaMalloc allowed): Wc for all 12 steps (~222 MB) + accumulators
__device__ float g_Wc[(size_t)KSTEPS*WC_PER_K];
__device__ float g_loss_sum[KSTEPS];
__device__ float g_acc_sum[KSTEPS];

// -------------------------------------------------------------------------
// Reset accumulators (graph replay must be deterministic)
__global__ void zero_sums_kernel() {
    int t = threadIdx.x;
    if (t < KSTEPS) { g_loss_sum[t] = 0.f; g_acc_sum[t] = 0.f; }
}

// -------------------------------------------------------------------------
// GEMM: Wc[k, m, n] = sum_kc c[su, l, kc] * W[k, n, kc] + b[k, n]
//   m = su*LEN + l  (note: c has T_=1140 rows per su, we use l < 1128)
// Tile: 128(M) x 64(N), K-chunks of 32. 256 threads, 8x4 micro-tile/thread.
__global__ __launch_bounds__(256)
void gemm_wc_kernel(const float* __restrict__ c,
                    const float* __restrict__ W,
                    const float* __restrict__ b) {
    const int k  = blockIdx.x;          // k fastest -> c tile reused in L2 across 12 k's
    const int m0 = blockIdx.y * 128;

    __shared__ float sA[128 * 33];      // [row][kc] stride 33 (conflict-free scalar ops)
    __shared__ float sB[64 * 33];       // [n][kc]   stride 33

    const int tid  = threadIdx.x;
    const int tx   = tid & 15;          // 0..15 -> n0 = tx*4
    const int ty   = tid >> 4;          // 0..15 -> r0 = ty*8
    const int n0   = tx * 4;
    const int r0   = ty * 8;
    const int base = tid >> 3;          // 0..31 (loader row group)
    const int c4   = tid & 7;           // 0..7  (float4 column within 32-wide chunk)

    // Per-thread A-row base pointers (4 rows, fixed across K loop)
    const float* aptr[4];
#pragma unroll
    for (int i = 0; i < 4; i++) {
        int m  = m0 + base + 32 * i;
        int su = m / LEN;
        int l  = m - su * LEN;
        aptr[i] = c + ((size_t)(su * T_ + l)) * CD + c4 * 4;
    }
    const float* bptr = W + (size_t)k * ZD * CD + c4 * 4;

    float acc[8][4];
#pragma unroll
    for (int i = 0; i < 8; i++)
#pragma unroll
        for (int j = 0; j < 4; j++) acc[i][j] = 0.f;

    for (int kk = 0; kk < CD; kk += 32) {
#pragma unroll
        for (int i = 0; i < 4; i++) {
            float4 v = *(const float4*)(aptr[i] + kk);
            float* d = &sA[(base + 32 * i) * 33 + c4 * 4];
            d[0] = v.x; d[1] = v.y; d[2] = v.z; d[3] = v.w;
        }
#pragma unroll
        for (int j = 0; j < 2; j++) {
            int nB   = base + 32 * j;
            float4 v = *(const float4*)(bptr + (size_t)nB * CD + kk);
            float* d = &sB[nB * 33 + c4 * 4];
            d[0] = v.x; d[1] = v.y; d[2] = v.z; d[3] = v.w;
        }
        __syncthreads();
#pragma unroll
        for (int kc = 0; kc < 32; kc++) {
            float a[8], bb[4];
#pragma unroll
            for (int i = 0; i < 8; i++) a[i] = sA[(r0 + i) * 33 + kc];
#pragma unroll
            for (int j = 0; j < 4; j++) bb[j] = sB[(n0 + j) * 33 + kc];
#pragma unroll
            for (int i = 0; i < 8; i++)
#pragma unroll
                for (int j = 0; j < 4; j++)
                    acc[i][j] = fmaf(a[i], bb[j], acc[i][j]);
        }
        __syncthreads();
    }

    float4 bias = *(const float4*)(b + k * ZD + n0);
    float* outk = g_Wc + (size_t)k * WC_PER_K;
#pragma unroll
    for (int i = 0; i < 8; i++) {
        int m = m0 + r0 + i;
        float4 o;
        o.x = acc[i][0] + bias.x;
        o.y = acc[i][1] + bias.y;
        o.z = acc[i][2] + bias.z;
        o.w = acc[i][3] + bias.w;
        *(float4*)(outk + (size_t)m * ZD + n0) = o;
    }
}

// -------------------------------------------------------------------------
// Scoring: one warp per l. Lane owns 2 of the 64 dims (coalesced 256B row
// gathers). 18 partial dots -> butterfly all-reduce -> logsumexp + argmax.
__global__ __launch_bounds__(256)
void score_kernel(const float* __restrict__ z,
                  const int* __restrict__ batch_index,
                  const int* __restrict__ seq_index) {
    const int by   = blockIdx.y;
    const int k    = by >> 6;           // 0..11
    const int su   = by & 63;
    const int s    = su >> 3;
    const int u    = su & 7;
    const int warp = threadIdx.x >> 5;
    const int lane = threadIdx.x & 31;
    const int l    = blockIdx.x * 8 + warp;   // 141*8 = 1128 exactly

    __shared__ float s_loss, s_acc;
    if (threadIdx.x == 0) { s_loss = 0.f; s_acc = 0.f; }
    __syncthreads();

    // Wc row and positive z row (coalesced float2 per lane)
    const float2* wc2 = (const float2*)(g_Wc + (size_t)k * WC_PER_K +
                                        (size_t)(su * LEN + l) * ZD);
    float2 w  = wc2[lane];
    const float2* zp = (const float2*)(z + (size_t)(su * T_ + (l + k + 1)) * ZD);
    float2 zv = zp[lane];

    float p[18];
    p[0] = zv.x * w.x + zv.y * w.y;

    const int* bi = batch_index + (k * U_ + u) * NEG;
    const int* si = seq_index + ((size_t)((k * S_ + s) * U_ + u) * NEG) * LEN + l;

#pragma unroll
    for (int n = 0; n < NEG; n++) {
        int bn = __ldg(bi + n);                 // uniform across warp
        int sn = __ldg(si + (size_t)n * LEN);   // uniform across warp
        const float2* zn = (const float2*)(z +
            (size_t)((s * U_ + bn) * T_ + (k + 1 + sn)) * ZD);
        float2 zr = zn[lane];
        p[1 + n] = zr.x * w.x + zr.y * w.y;
    }

    // Butterfly all-reduce over 32 lanes for the 18 partial dots
#pragma unroll
    for (int off = 16; off >= 1; off >>= 1) {
#pragma unroll
        for (int n = 0; n < 18; n++)
            p[n] += __shfl_xor_sync(0xffffffffu, p[n], off);
    }

    if (lane == 0) {
        float f[18];
#pragma unroll
        for (int n = 0; n < 18; n++) f[n] = p[n] * 0.125f;   // 1/sqrt(64)
        // argmax with first-occurrence tie-break (matches jnp.argmax)
        float m = f[0]; int arg = 0;
#pragma unroll
        for (int n = 1; n < 18; n++)
            if (f[n] > m) { m = f[n]; arg = n; }
        float se = 0.f;
#pragma unroll
        for (int n = 0; n < 18; n++) se += __expf(f[n] - m);
        float lse = m + __logf(se);
        atomicAdd(&s_loss, lse - f[0]);
        atomicAdd(&s_acc, (arg == 0) ? 1.f : 0.f);
    }
    __syncthreads();
    if (threadIdx.x == 0) {
        atomicAdd(&g_loss_sum[k], s_loss);
        atomicAdd(&g_acc_sum[k], s_acc);
    }
}

// -------------------------------------------------------------------------
__global__ void finalize_kernel(float* __restrict__ out, int out_size) {
    __shared__ float sl[KSTEPS];
    int t = threadIdx.x;
    const float inv = 1.f / (float)(SU * LEN);
    if (t < KSTEPS) {
        sl[t] = g_loss_sum[t] * inv;
        if (1 + t < out_size) out[1 + t] = g_acc_sum[t] * inv;
    }
    __syncthreads();
    if (t == 0 && out_size > 0) {
        float sum = 0.f;
        for (int i = 0; i < KSTEPS; i++) sum += sl[i];
        out[0] = sum * (1.f / (float)KSTEPS);
    }
    for (int i = 13 + t; i < out_size; i += blockDim.x) out[i] = 0.f;
}

// -------------------------------------------------------------------------
extern "C" void kernel_launch(void* const* d_in, const int* in_sizes, int n_in,
                              void* d_out, int out_size) {
    const float* z           = (const float*)d_in[0];
    const float* c           = (const float*)d_in[1];
    const float* W           = (const float*)d_in[2];
    const float* b           = (const float*)d_in[3];
    const int*   batch_index = (const int*)d_in[4];
    const int*   seq_index   = (const int*)d_in[5];

    zero_sums_kernel<<<1, 32>>>();

    dim3 g1(KSTEPS, MROWS / 128);       // k fastest for L2 reuse of c tiles
    gemm_wc_kernel<<<g1, 256>>>(c, W, b);

    dim3 g2(LEN / 8, KSTEPS * SU);      // 141 x 768
    score_kernel<<<g2, 256>>>(z, batch_index, seq_index);

    finalize_kernel<<<1, 64>>>((float*)d_out, out_size);
}

// round 3
// speedup vs baseline: 1.3177x; 1.3177x over previous
#include <cuda_runtime.h>
#include <math.h>

// Problem constants
#define S_      8
#define U_      8
#define KSTEPS  12
#define NEG     17
#define ZD      64
#define CD      256
#define T_      1140
#define LEN     1128
#define SU      64              // S_*U_
#define MROWS   (SU*LEN)        // 72192
#define WC_PER_K ((size_t)MROWS*ZD)   // 4,620,288 floats per k

// Scratch (no cudaMalloc allowed): Wc for all 12 steps (~222 MB) + accumulators
__device__ float g_Wc[(size_t)KSTEPS*WC_PER_K];
__device__ float g_loss_sum[KSTEPS];
__device__ float g_acc_sum[KSTEPS];

// -------------------------------------------------------------------------
__global__ void zero_sums_kernel() {
    int t = threadIdx.x;
    if (t < KSTEPS) { g_loss_sum[t] = 0.f; g_acc_sum[t] = 0.f; }
}

// -------------------------------------------------------------------------
// tf32 destination is a .b32 register in PTX ("=r", not "=f")
__device__ __forceinline__ float f2tf32(float x) {
    unsigned r;
    asm("cvt.rna.tf32.f32 %0, %1;" : "=r"(r) : "f"(x));
    return __uint_as_float(r);
}

// GEMM via tf32 mma.sync: Wc[k, m, n] = sum_kc c[su,l,kc] * W[k,n,kc] + b[k,n]
// Block tile 128(M) x 64(N), K chunks of 32 in smem (stride 36 -> conflict-free
// fragment loads). 8 warps, each warp: 16 rows x full N=64 (8 n-frags).
__global__ __launch_bounds__(256)
void gemm_wc_tf32(const float* __restrict__ c,
                  const float* __restrict__ W,
                  const float* __restrict__ b) {
    const int k  = blockIdx.x;          // k fastest -> c tile reused in L2 across 12 k's
    const int m0 = blockIdx.y * 128;

    __shared__ float sA[128 * 36];      // stride 36: bank = (4*row + kc) % 32, conflict-free frags
    __shared__ float sB[64 * 36];

    const int tid  = threadIdx.x;
    const int warp = tid >> 5;
    const int lane = tid & 31;
    const int grp  = lane >> 2;         // 0..7
    const int tig  = lane & 3;          // 0..3
    const int mw   = warp * 16;         // warp row base within block tile

    const int base = tid >> 3;          // 0..31 loader row
    const int c4   = tid & 7;           // 0..7  float4 col

    // Per-thread A-row base pointers (4 rows, fixed across K loop)
    const float* aptr[4];
#pragma unroll
    for (int i = 0; i < 4; i++) {
        int m  = m0 + base + 32 * i;
        int su = m / LEN;
        int l  = m - su * LEN;
        aptr[i] = c + ((size_t)(su * T_ + l)) * CD + c4 * 4;
    }
    const float* bptr = W + (size_t)k * ZD * CD + c4 * 4;

    float acc[8][4];
#pragma unroll
    for (int j = 0; j < 8; j++)
#pragma unroll
        for (int i = 0; i < 4; i++) acc[j][i] = 0.f;

    for (int kk = 0; kk < CD; kk += 32) {
        // ---- load + tf32-convert A (128x32) and B (64x32) into smem ----
#pragma unroll
        for (int i = 0; i < 4; i++) {
            float4 v = *(const float4*)(aptr[i] + kk);
            float* d = &sA[(base + 32 * i) * 36 + c4 * 4];
            d[0] = f2tf32(v.x); d[1] = f2tf32(v.y);
            d[2] = f2tf32(v.z); d[3] = f2tf32(v.w);
        }
#pragma unroll
        for (int j = 0; j < 2; j++) {
            int nB   = base + 32 * j;
            float4 v = *(const float4*)(bptr + (size_t)nB * CD + kk);
            float* d = &sB[nB * 36 + c4 * 4];
            d[0] = f2tf32(v.x); d[1] = f2tf32(v.y);
            d[2] = f2tf32(v.z); d[3] = f2tf32(v.w);
        }
        __syncthreads();

        // ---- 4 k-steps of 8 ----
#pragma unroll
        for (int ks = 0; ks < 4; ks++) {
            const int kc0 = ks * 8;
            // A fragment (m16 k8): rows mw+grp, mw+grp+8; cols kc0+tig, kc0+tig+4
            const float* ar = &sA[(mw + grp) * 36 + kc0 + tig];
            unsigned a0 = __float_as_uint(ar[0]);
            unsigned a1 = __float_as_uint(ar[8 * 36]);
            unsigned a2 = __float_as_uint(ar[4]);
            unsigned a3 = __float_as_uint(ar[8 * 36 + 4]);
#pragma unroll
            for (int j = 0; j < 8; j++) {
                const float* br = &sB[(8 * j + grp) * 36 + kc0 + tig];
                unsigned b0 = __float_as_uint(br[0]);
                unsigned b1 = __float_as_uint(br[4]);
                asm volatile(
                    "mma.sync.aligned.m16n8k8.row.col.f32.tf32.tf32.f32 "
                    "{%0,%1,%2,%3}, {%4,%5,%6,%7}, {%8,%9}, {%0,%1,%2,%3};\n"
                    : "+f"(acc[j][0]), "+f"(acc[j][1]),
                      "+f"(acc[j][2]), "+f"(acc[j][3])
                    : "r"(a0), "r"(a1), "r"(a2), "r"(a3), "r"(b0), "r"(b1));
            }
        }
        __syncthreads();
    }

    // ---- epilogue: add bias, store float2 per fragment row ----
    float* outk = g_Wc + (size_t)k * WC_PER_K;
    const int m_lo = m0 + mw + grp;
#pragma unroll
    for (int j = 0; j < 8; j++) {
        const int n = 8 * j + 2 * tig;
        float2 bias = *(const float2*)(b + k * ZD + n);
        float2 o0, o1;
        o0.x = acc[j][0] + bias.x; o0.y = acc[j][1] + bias.y;
        o1.x = acc[j][2] + bias.x; o1.y = acc[j][3] + bias.y;
        *(float2*)(outk + (size_t)m_lo * ZD + n)       = o0;
        *(float2*)(outk + (size_t)(m_lo + 8) * ZD + n) = o1;
    }
}

// -------------------------------------------------------------------------
// Scoring: one warp per l. Lane owns 2 of the 64 dims (coalesced 256B row
// gathers). 18 partial dots -> butterfly all-reduce -> logsumexp + argmax.
__global__ __launch_bounds__(256)
void score_kernel(const float* __restrict__ z,
                  const int* __restrict__ batch_index,
                  const int* __restrict__ seq_index) {
    const int by   = blockIdx.y;
    const int k    = by >> 6;           // 0..11
    const int su   = by & 63;
    const int s    = su >> 3;
    const int u    = su & 7;
    const int warp = threadIdx.x >> 5;
    const int lane = threadIdx.x & 31;
    const int l    = blockIdx.x * 8 + warp;   // 141*8 = 1128 exactly

    __shared__ float s_loss, s_acc;
    if (threadIdx.x == 0) { s_loss = 0.f; s_acc = 0.f; }
    __syncthreads();

    const float2* wc2 = (const float2*)(g_Wc + (size_t)k * WC_PER_K +
                                        (size_t)(su * LEN + l) * ZD);
    float2 w  = wc2[lane];
    const float2* zp = (const float2*)(z + (size_t)(su * T_ + (l + k + 1)) * ZD);
    float2 zv = zp[lane];

    float p[18];
    p[0] = zv.x * w.x + zv.y * w.y;

    const int* bi = batch_index + (k * U_ + u) * NEG;
    const int* si = seq_index + ((size_t)((k * S_ + s) * U_ + u) * NEG) * LEN + l;

#pragma unroll
    for (int n = 0; n < NEG; n++) {
        int bn = __ldg(bi + n);                 // uniform across warp
        int sn = __ldg(si + (size_t)n * LEN);   // uniform across warp
        const float2* zn = (const float2*)(z +
            (size_t)((s * U_ + bn) * T_ + (k + 1 + sn)) * ZD);
        float2 zr = zn[lane];
        p[1 + n] = zr.x * w.x + zr.y * w.y;
    }

#pragma unroll
    for (int off = 16; off >= 1; off >>= 1) {
#pragma unroll
        for (int n = 0; n < 18; n++)
            p[n] += __shfl_xor_sync(0xffffffffu, p[n], off);
    }

    if (lane == 0) {
        float f[18];
#pragma unroll
        for (int n = 0; n < 18; n++) f[n] = p[n] * 0.125f;   // 1/sqrt(64)
        float m = f[0]; int arg = 0;
#pragma unroll
        for (int n = 1; n < 18; n++)
            if (f[n] > m) { m = f[n]; arg = n; }
        float se = 0.f;
#pragma unroll
        for (int n = 0; n < 18; n++) se += __expf(f[n] - m);
        float lse = m + __logf(se);
        atomicAdd(&s_loss, lse - f[0]);
        atomicAdd(&s_acc, (arg == 0) ? 1.f : 0.f);
    }
    __syncthreads();
    if (threadIdx.x == 0) {
        atomicAdd(&g_loss_sum[k], s_loss);
        atomicAdd(&g_acc_sum[k], s_acc);
    }
}

// -------------------------------------------------------------------------
__global__ void finalize_kernel(float* __restrict__ out, int out_size) {
    __shared__ float sl[KSTEPS];
    int t = threadIdx.x;
    const float inv = 1.f / (float)(SU * LEN);
    if (t < KSTEPS) {
        sl[t] = g_loss_sum[t] * inv;
        if (1 + t < out_size) out[1 + t] = g_acc_sum[t] * inv;
    }
    __syncthreads();
    if (t == 0 && out_size > 0) {
        float sum = 0.f;
        for (int i = 0; i < KSTEPS; i++) sum += sl[i];
        out[0] = sum * (1.f / (float)KSTEPS);
    }
    for (int i = 13 + t; i < out_size; i += blockDim.x) out[i] = 0.f;
}

// -------------------------------------------------------------------------
extern "C" void kernel_launch(void* const* d_in, const int* in_sizes, int n_in,
                              void* d_out, int out_size) {
    const float* z           = (const float*)d_in[0];
    const float* c           = (const float*)d_in[1];
    const float* W           = (const float*)d_in[2];
    const float* b           = (const float*)d_in[3];
    const int*   batch_index = (const int*)d_in[4];
    const int*   seq_index   = (const int*)d_in[5];

    zero_sums_kernel<<<1, 32>>>();

    dim3 g1(KSTEPS, MROWS / 128);       // k fastest for L2 reuse of c tiles
    gemm_wc_tf32<<<g1, 256>>>(c, W, b);

    dim3 g2(LEN / 8, KSTEPS * SU);      // 141 x 768
    score_kernel<<<g2, 256>>>(z, batch_index, seq_index);

    finalize_kernel<<<1, 64>>>((float*)d_out, out_size);
}

// round 4
// speedup vs baseline: 1.4575x; 1.1061x over previous
#include <cuda_runtime.h>
#include <math.h>

// Problem constants
#define S_      8
#define U_      8
#define KSTEPS  12
#define NEG     17
#define ZD      64
#define CD      256
#define T_      1140
#define LEN     1128
#define SU      64              // S_*U_
#define MROWS   (SU*LEN)        // 72192
#define NTILES  (MROWS/128)     // 564
#define WCSTR   68              // smem Wc row stride (floats): conflict-free + 8B aligned

__device__ float g_loss_sum[KSTEPS];
__device__ float g_acc_sum[KSTEPS];

// -------------------------------------------------------------------------
__global__ void zero_sums_kernel() {
    int t = threadIdx.x;
    if (t < KSTEPS) { g_loss_sum[t] = 0.f; g_acc_sum[t] = 0.f; }
}

// -------------------------------------------------------------------------
__device__ __forceinline__ float f2tf32(float x) {
    unsigned r;
    asm("cvt.rna.tf32.f32 %0, %1;" : "=r"(r) : "f"(x));
    return __uint_as_float(r);
}

// -------------------------------------------------------------------------
// Fused kernel: per CTA, compute one 128(M) x 64(N) Wc tile for one k via
// tf32 mma.sync into registers, park it in smem, then score those 128
// (su,l) rows (pos + 17 gathered negatives) and accumulate loss/acc.
// smem: sA(18432B)+sB(9216B) overlaid by sWc(34816B) after the k-loop.
__global__ __launch_bounds__(256, 2)
void fused_kernel(const float* __restrict__ z,
                  const float* __restrict__ c,
                  const float* __restrict__ W,
                  const float* __restrict__ bias,
                  const int* __restrict__ batch_index,
                  const int* __restrict__ seq_index) {
    __shared__ __align__(16) char smem_u[128 * WCSTR * 4];   // 34816 B union
    __shared__ float s_loss, s_acc;

    float* sA  = (float*)smem_u;            // [128][36]
    float* sB  = sA + 128 * 36;             // [64][36]
    float* sWc = (float*)smem_u;            // [128][WCSTR] (overlays sA/sB later)

    const int bx = blockIdx.x;
    const int k  = bx % KSTEPS;             // k fastest -> c tile L2 reuse
    const int m0 = (bx / KSTEPS) * 128;

    const int tid  = threadIdx.x;
    const int warp = tid >> 5;
    const int lane = tid & 31;
    const int grp  = lane >> 2;             // 0..7
    const int tig  = lane & 3;              // 0..3
    const int mw   = warp * 16;

    if (tid == 0) { s_loss = 0.f; s_acc = 0.f; }

    // ---------------- GEMM phase (tf32 mma.sync) ----------------
    const int base = tid >> 3;              // 0..31 loader row
    const int c4   = tid & 7;               // 0..7  float4 col

    const float* aptr[4];
#pragma unroll
    for (int i = 0; i < 4; i++) {
        int m  = m0 + base + 32 * i;
        int su = m / LEN;
        int l  = m - su * LEN;
        aptr[i] = c + ((size_t)(su * T_ + l)) * CD + c4 * 4;
    }
    const float* bptr = W + (size_t)k * ZD * CD + c4 * 4;

    float acc[8][4];
#pragma unroll
    for (int j = 0; j < 8; j++)
#pragma unroll
        for (int i = 0; i < 4; i++) acc[j][i] = 0.f;

    for (int kk = 0; kk < CD; kk += 32) {
#pragma unroll
        for (int i = 0; i < 4; i++) {
            float4 v = *(const float4*)(aptr[i] + kk);
            float* d = &sA[(base + 32 * i) * 36 + c4 * 4];
            d[0] = f2tf32(v.x); d[1] = f2tf32(v.y);
            d[2] = f2tf32(v.z); d[3] = f2tf32(v.w);
        }
#pragma unroll
        for (int j = 0; j < 2; j++) {
            int nB   = base + 32 * j;
            float4 v = *(const float4*)(bptr + (size_t)nB * CD + kk);
            float* d = &sB[nB * 36 + c4 * 4];
            d[0] = f2tf32(v.x); d[1] = f2tf32(v.y);
            d[2] = f2tf32(v.z); d[3] = f2tf32(v.w);
        }
        __syncthreads();
#pragma unroll
        for (int ks = 0; ks < 4; ks++) {
            const int kc0 = ks * 8;
            const float* ar = &sA[(mw + grp) * 36 + kc0 + tig];
            unsigned a0 = __float_as_uint(ar[0]);
            unsigned a1 = __float_as_uint(ar[8 * 36]);
            unsigned a2 = __float_as_uint(ar[4]);
            unsigned a3 = __float_as_uint(ar[8 * 36 + 4]);
#pragma unroll
            for (int j = 0; j < 8; j++) {
                const float* br = &sB[(8 * j + grp) * 36 + kc0 + tig];
                unsigned b0 = __float_as_uint(br[0]);
                unsigned b1 = __float_as_uint(br[4]);
                asm volatile(
                    "mma.sync.aligned.m16n8k8.row.col.f32.tf32.tf32.f32 "
                    "{%0,%1,%2,%3}, {%4,%5,%6,%7}, {%8,%9}, {%0,%1,%2,%3};\n"
                    : "+f"(acc[j][0]), "+f"(acc[j][1]),
                      "+f"(acc[j][2]), "+f"(acc[j][3])
                    : "r"(a0), "r"(a1), "r"(a2), "r"(a3), "r"(b0), "r"(b1));
            }
        }
        __syncthreads();
    }

    // ---------------- epilogue: bias + park Wc tile in smem ----------------
    // (sA/sB dead after the final __syncthreads above; sWc overlays them)
#pragma unroll
    for (int j = 0; j < 8; j++) {
        const int n = 8 * j + 2 * tig;
        float2 bb = *(const float2*)(bias + k * ZD + n);
        float2 o0, o1;
        o0.x = acc[j][0] + bb.x; o0.y = acc[j][1] + bb.y;
        o1.x = acc[j][2] + bb.x; o1.y = acc[j][3] + bb.y;
        *(float2*)(sWc + (size_t)(mw + grp) * WCSTR + n)       = o0;
        *(float2*)(sWc + (size_t)(mw + grp + 8) * WCSTR + n)   = o1;
    }
    __syncthreads();

    // ---------------- scoring phase: 16 rows per warp ----------------
    float warp_loss = 0.f, warp_acc = 0.f;

    for (int j = 0; j < 16; j++) {
        const int r  = warp * 16 + j;
        const int m  = m0 + r;
        const int su = m / LEN;
        const int l  = m - su * LEN;
        const int s  = su >> 3;
        const int u  = su & 7;

        const float2* w2 = (const float2*)(sWc + (size_t)r * WCSTR);
        float2 w = w2[lane];

        const float2* zp = (const float2*)(z + (size_t)(su * T_ + (l + k + 1)) * ZD);
        float2 zv = zp[lane];

        float p[18];
        p[0] = zv.x * w.x + zv.y * w.y;

        const int* bi = batch_index + (k * U_ + u) * NEG;
        const int* si = seq_index + ((size_t)((k * S_ + s) * U_ + u) * NEG) * LEN + l;

#pragma unroll
        for (int n = 0; n < NEG; n++) {
            int bn = __ldg(bi + n);                 // warp-uniform
            int sn = __ldg(si + (size_t)n * LEN);   // warp-uniform
            const float2* zn = (const float2*)(z +
                (size_t)((s * U_ + bn) * T_ + (k + 1 + sn)) * ZD);
            float2 zr = zn[lane];
            p[1 + n] = zr.x * w.x + zr.y * w.y;
        }

#pragma unroll
        for (int off = 16; off >= 1; off >>= 1) {
#pragma unroll
            for (int n = 0; n < 18; n++)
                p[n] += __shfl_xor_sync(0xffffffffu, p[n], off);
        }

        if (lane == 0) {
            float f[18];
#pragma unroll
            for (int n = 0; n < 18; n++) f[n] = p[n] * 0.125f;   // 1/sqrt(64)
            float mx = f[0]; int arg = 0;
#pragma unroll
            for (int n = 1; n < 18; n++)
                if (f[n] > mx) { mx = f[n]; arg = n; }
            float se = 0.f;
#pragma unroll
            for (int n = 0; n < 18; n++) se += __expf(f[n] - mx);
            warp_loss += (mx + __logf(se)) - f[0];
            warp_acc  += (arg == 0) ? 1.f : 0.f;
        }
    }

    if (lane == 0) {
        atomicAdd(&s_loss, warp_loss);
        atomicAdd(&s_acc, warp_acc);
    }
    __syncthreads();
    if (tid == 0) {
        atomicAdd(&g_loss_sum[k], s_loss);
        atomicAdd(&g_acc_sum[k], s_acc);
    }
}

// -------------------------------------------------------------------------
__global__ void finalize_kernel(float* __restrict__ out, int out_size) {
    __shared__ float sl[KSTEPS];
    int t = threadIdx.x;
    const float inv = 1.f / (float)(SU * LEN);
    if (t < KSTEPS) {
        sl[t] = g_loss_sum[t] * inv;
        if (1 + t < out_size) out[1 + t] = g_acc_sum[t] * inv;
    }
    __syncthreads();
    if (t == 0 && out_size > 0) {
        float sum = 0.f;
        for (int i = 0; i < KSTEPS; i++) sum += sl[i];
        out[0] = sum * (1.f / (float)KSTEPS);
    }
    for (int i = 13 + t; i < out_size; i += blockDim.x) out[i] = 0.f;
}

// -------------------------------------------------------------------------
extern "C" void kernel_launch(void* const* d_in, const int* in_sizes, int n_in,
                              void* d_out, int out_size) {
    const float* z           = (const float*)d_in[0];
    const float* c           = (const float*)d_in[1];
    const float* W           = (const float*)d_in[2];
    const float* b           = (const float*)d_in[3];
    const int*   batch_index = (const int*)d_in[4];
    const int*   seq_index   = (const int*)d_in[5];

    zero_sums_kernel<<<1, 32>>>();
    fused_kernel<<<NTILES * KSTEPS, 256>>>(z, c, W, b, batch_index, seq_index);
    finalize_kernel<<<1, 64>>>((float*)d_out, out_size);
}

// round 5
// speedup vs baseline: 2.2947x; 1.5744x over previous
#include <cuda_runtime.h>
#include <math.h>

// Problem constants
#define S_      8
#define U_      8
#define KSTEPS  12
#define NEG     17
#define ZD      64
#define CD      256
#define T_      1140
#define LEN     1128
#define SU      64              // S_*U_
#define MROWS   (SU*LEN)        // 72192
#define NTILES  (MROWS/128)     // 564
#define WCSTR   72              // smem Wc row stride (floats)

__device__ float g_loss_sum[KSTEPS];
__device__ float g_acc_sum[KSTEPS];

// -------------------------------------------------------------------------
__global__ void zero_sums_kernel() {
    int t = threadIdx.x;
    if (t < KSTEPS) { g_loss_sum[t] = 0.f; g_acc_sum[t] = 0.f; }
}

// -------------------------------------------------------------------------
__device__ __forceinline__ float f2tf32(float x) {
    unsigned r;
    asm("cvt.rna.tf32.f32 %0, %1;" : "=r"(r) : "f"(x));
    return __uint_as_float(r);
}

__device__ __forceinline__ float dot8(float4 a0, float4 a1, float4 b0, float4 b1) {
    float s = a0.x * b0.x;
    s = fmaf(a0.y, b0.y, s);
    s = fmaf(a0.z, b0.z, s);
    s = fmaf(a0.w, b0.w, s);
    s = fmaf(a1.x, b1.x, s);
    s = fmaf(a1.y, b1.y, s);
    s = fmaf(a1.z, b1.z, s);
    s = fmaf(a1.w, b1.w, s);
    return s;
}

// -------------------------------------------------------------------------
// Fused: per CTA compute one 128x64 Wc tile (tf32 mma) into smem, then score
// those 128 rows. Scoring is quad-parallel: 4 rows per warp iteration, 8 lanes
// per row (each lane owns 8 of the 64 dims), 3-round butterfly reduction.
__global__ __launch_bounds__(256, 2)
void fused_kernel(const float* __restrict__ z,
                  const float* __restrict__ c,
                  const float* __restrict__ W,
                  const float* __restrict__ bias,
                  const int* __restrict__ batch_index,
                  const int* __restrict__ seq_index) {
    __shared__ __align__(16) char smem_u[128 * WCSTR * 4];   // 36864 B union
    __shared__ float s_loss, s_acc;

    float* sA  = (float*)smem_u;            // [128][36]
    float* sB  = sA + 128 * 36;             // [64][36]
    float* sWc = (float*)smem_u;            // [128][WCSTR] overlays sA/sB later

    const int bx = blockIdx.x;
    const int k  = bx % KSTEPS;             // k fastest -> c tile L2 reuse
    const int m0 = (bx / KSTEPS) * 128;

    const int tid  = threadIdx.x;
    const int warp = tid >> 5;
    const int lane = tid & 31;
    const int grp  = lane >> 2;             // 0..7 (mma)
    const int tig  = lane & 3;              // 0..3 (mma)
    const int mw   = warp * 16;

    if (tid == 0) { s_loss = 0.f; s_acc = 0.f; }

    // ---------------- GEMM phase (tf32 mma.sync) ----------------
    const int base = tid >> 3;              // 0..31 loader row
    const int c4   = tid & 7;               // 0..7  float4 col

    const float* aptr[4];
#pragma unroll
    for (int i = 0; i < 4; i++) {
        int m  = m0 + base + 32 * i;
        int su = m / LEN;
        int l  = m - su * LEN;
        aptr[i] = c + ((size_t)(su * T_ + l)) * CD + c4 * 4;
    }
    const float* bptr = W + (size_t)k * ZD * CD + c4 * 4;

    float acc[8][4];
#pragma unroll
    for (int j = 0; j < 8; j++)
#pragma unroll
        for (int i = 0; i < 4; i++) acc[j][i] = 0.f;

    for (int kk = 0; kk < CD; kk += 32) {
#pragma unroll
        for (int i = 0; i < 4; i++) {
            float4 v = *(const float4*)(aptr[i] + kk);
            float* d = &sA[(base + 32 * i) * 36 + c4 * 4];
            d[0] = f2tf32(v.x); d[1] = f2tf32(v.y);
            d[2] = f2tf32(v.z); d[3] = f2tf32(v.w);
        }
#pragma unroll
        for (int j = 0; j < 2; j++) {
            int nB   = base + 32 * j;
            float4 v = *(const float4*)(bptr + (size_t)nB * CD + kk);
            float* d = &sB[nB * 36 + c4 * 4];
            d[0] = f2tf32(v.x); d[1] = f2tf32(v.y);
            d[2] = f2tf32(v.z); d[3] = f2tf32(v.w);
        }
        __syncthreads();
#pragma unroll
        for (int ks = 0; ks < 4; ks++) {
            const int kc0 = ks * 8;
            const float* ar = &sA[(mw + grp) * 36 + kc0 + tig];
            unsigned a0 = __float_as_uint(ar[0]);
            unsigned a1 = __float_as_uint(ar[8 * 36]);
            unsigned a2 = __float_as_uint(ar[4]);
            unsigned a3 = __float_as_uint(ar[8 * 36 + 4]);
#pragma unroll
            for (int j = 0; j < 8; j++) {
                const float* br = &sB[(8 * j + grp) * 36 + kc0 + tig];
                unsigned b0 = __float_as_uint(br[0]);
                unsigned b1 = __float_as_uint(br[4]);
                asm volatile(
                    "mma.sync.aligned.m16n8k8.row.col.f32.tf32.tf32.f32 "
                    "{%0,%1,%2,%3}, {%4,%5,%6,%7}, {%8,%9}, {%0,%1,%2,%3};\n"
                    : "+f"(acc[j][0]), "+f"(acc[j][1]),
                      "+f"(acc[j][2]), "+f"(acc[j][3])
                    : "r"(a0), "r"(a1), "r"(a2), "r"(a3), "r"(b0), "r"(b1));
            }
        }
        __syncthreads();
    }

    // ---------------- epilogue: bias + park Wc tile in smem ----------------
#pragma unroll
    for (int j = 0; j < 8; j++) {
        const int n = 8 * j + 2 * tig;
        float2 bb = *(const float2*)(bias + k * ZD + n);
        float2 o0, o1;
        o0.x = acc[j][0] + bb.x; o0.y = acc[j][1] + bb.y;
        o1.x = acc[j][2] + bb.x; o1.y = acc[j][3] + bb.y;
        *(float2*)(sWc + (size_t)(mw + grp) * WCSTR + n)     = o0;
        *(float2*)(sWc + (size_t)(mw + grp + 8) * WCSTR + n) = o1;
    }
    __syncthreads();

    // ---------------- scoring phase: quad-parallel, 4 rows/warp-iter -------
    const int quad = lane >> 3;             // 0..3 : which row of the group
    const int lq   = lane & 7;              // 0..7 : lane within quad (8 dims each)

    float warp_loss = 0.f, warp_acc = 0.f;  // valid at quad leaders (lq==0)

#pragma unroll
    for (int it = 0; it < 4; it++) {
        const int r  = mw + it * 4 + quad;
        const int m  = m0 + r;
        const int su = m / LEN;
        const int l  = m - su * LEN;
        const int s  = su >> 3;
        const int u  = su & 7;

        // Wc fragment: 8 dims per lane
        const float4* w4 = (const float4*)(sWc + (size_t)r * WCSTR + lq * 8);
        float4 w0 = w4[0], w1 = w4[1];

        // positive z row
        const float4* zp = (const float4*)(z +
            (size_t)(su * T_ + (l + k + 1)) * ZD + lq * 8);
        float4 z0 = zp[0], z1 = zp[1];

        float p[18];
        p[0] = dot8(z0, z1, w0, w1);

        // preload this quad's neg indices: lane lq holds n = lq, lq+8, lq+16
        const int* bi = batch_index + (k * U_ + u) * NEG;
        const int* si = seq_index + ((size_t)((k * S_ + s) * U_ + u) * NEG) * LEN + l;
        int bn_r[3], sn_r[3];
#pragma unroll
        for (int j = 0; j < 3; j++) {
            int n = lq + 8 * j;
            if (n < NEG) {
                bn_r[j] = __ldg(bi + n);
                sn_r[j] = __ldg(si + (size_t)n * LEN);
            } else { bn_r[j] = 0; sn_r[j] = 0; }
        }

#pragma unroll
        for (int n = 0; n < NEG; n++) {
            int bn = __shfl_sync(0xffffffffu, bn_r[n >> 3], n & 7, 8);
            int sn = __shfl_sync(0xffffffffu, sn_r[n >> 3], n & 7, 8);
            const float4* zn = (const float4*)(z +
                (size_t)((s * U_ + bn) * T_ + (k + 1 + sn)) * ZD + lq * 8);
            float4 a0 = zn[0], a1 = zn[1];
            p[1 + n] = dot8(a0, a1, w0, w1);
        }

        // 3-round butterfly within each quad
#pragma unroll
        for (int off = 4; off >= 1; off >>= 1) {
#pragma unroll
            for (int n = 0; n < 18; n++)
                p[n] += __shfl_xor_sync(0xffffffffu, p[n], off);
        }

        if (lq == 0) {     // 4 quad leaders execute these instructions together
            float f0 = p[0] * 0.125f;
            float mxn = p[1];
#pragma unroll
            for (int n = 2; n < 18; n++) mxn = fmaxf(mxn, p[n]);
            mxn *= 0.125f;
            float mx = fmaxf(f0, mxn);
            float se = __expf(f0 - mx);
#pragma unroll
            for (int n = 1; n < 18; n++) se += __expf(p[n] * 0.125f - mx);
            warp_loss += (mx + __logf(se)) - f0;
            warp_acc  += (f0 >= mxn) ? 1.f : 0.f;   // argmax==0 (ties -> 0)
        }
    }

    // combine the 4 quad leaders (lanes 0,8,16,24)
    warp_loss += __shfl_xor_sync(0xffffffffu, warp_loss, 8);
    warp_loss += __shfl_xor_sync(0xffffffffu, warp_loss, 16);
    warp_acc  += __shfl_xor_sync(0xffffffffu, warp_acc, 8);
    warp_acc  += __shfl_xor_sync(0xffffffffu, warp_acc, 16);

    if (lane == 0) {
        atomicAdd(&s_loss, warp_loss);
        atomicAdd(&s_acc, warp_acc);
    }
    __syncthreads();
    if (tid == 0) {
        atomicAdd(&g_loss_sum[k], s_loss);
        atomicAdd(&g_acc_sum[k], s_acc);
    }
}

// -------------------------------------------------------------------------
__global__ void finalize_kernel(float* __restrict__ out, int out_size) {
    __shared__ float sl[KSTEPS];
    int t = threadIdx.x;
    const float inv = 1.f / (float)(SU * LEN);
    if (t < KSTEPS) {
        sl[t] = g_loss_sum[t] * inv;
        if (1 + t < out_size) out[1 + t] = g_acc_sum[t] * inv;
    }
    __syncthreads();
    if (t == 0 && out_size > 0) {
        float sum = 0.f;
        for (int i = 0; i < KSTEPS; i++) sum += sl[i];
        out[0] = sum * (1.f / (float)KSTEPS);
    }
    for (int i = 13 + t; i < out_size; i += blockDim.x) out[i] = 0.f;
}

// -------------------------------------------------------------------------
extern "C" void kernel_launch(void* const* d_in, const int* in_sizes, int n_in,
                              void* d_out, int out_size) {
    const float* z           = (const float*)d_in[0];
    const float* c           = (const float*)d_in[1];
    const float* W           = (const float*)d_in[2];
    const float* b           = (const float*)d_in[3];
    const int*   batch_index = (const int*)d_in[4];
    const int*   seq_index   = (const int*)d_in[5];

    zero_sums_kernel<<<1, 32>>>();
    fused_kernel<<<NTILES * KSTEPS, 256>>>(z, c, W, b, batch_index, seq_index);
    finalize_kernel<<<1, 64>>>((float*)d_out, out_size);
}

// round 8
// speedup vs baseline: 2.8649x; 1.2485x over previous
#include <cuda_runtime.h>
#include <cuda_fp16.h>
#include <math.h>

// Problem constants
#define S_      8
#define U_      8
#define KSTEPS  12
#define NEG     17
#define ZD      64
#define CD      256
#define T_      1140
#define LEN     1128
#define SU      64              // S_*U_
#define MROWS   (SU*LEN)        // 72192
#define NTILES  (MROWS/128)     // 564
#define WCSTR   72              // smem Wc row stride (floats)

__device__ float g_loss_sum[KSTEPS];
__device__ float g_acc_sum[KSTEPS];
__device__ __half g_zh[(size_t)SU * T_ * ZD];   // fp16 copy of z (9.3 MB)

// -------------------------------------------------------------------------
__global__ void zero_sums_kernel() {
    int t = threadIdx.x;
    if (t < KSTEPS) { g_loss_sum[t] = 0.f; g_acc_sum[t] = 0.f; }
}

// z -> fp16 (once per launch; deterministic)
__global__ void convert_z_kernel(const float* __restrict__ z) {
    size_t i = (size_t)blockIdx.x * blockDim.x + threadIdx.x;   // one float4
    const size_t n4 = (size_t)SU * T_ * ZD / 4;
    if (i < n4) {
        float4 v = ((const float4*)z)[i];
        __half2 h0 = __floats2half2_rn(v.x, v.y);
        __half2 h1 = __floats2half2_rn(v.z, v.w);
        uint2 o;
        o.x = *(unsigned*)&h0;
        o.y = *(unsigned*)&h1;
        ((uint2*)g_zh)[i] = o;
    }
}

// -------------------------------------------------------------------------
__device__ __forceinline__ float f2tf32(float x) {
    unsigned r;
    asm("cvt.rna.tf32.f32 %0, %1;" : "=r"(r) : "f"(x));
    return __uint_as_float(r);
}

__device__ __forceinline__ float dot8(float4 a0, float4 a1, float4 b0, float4 b1) {
    float s = a0.x * b0.x;
    s = fmaf(a0.y, b0.y, s);
    s = fmaf(a0.z, b0.z, s);
    s = fmaf(a0.w, b0.w, s);
    s = fmaf(a1.x, b1.x, s);
    s = fmaf(a1.y, b1.y, s);
    s = fmaf(a1.z, b1.z, s);
    s = fmaf(a1.w, b1.w, s);
    return s;
}

// -------------------------------------------------------------------------
// Fused: per CTA compute one 128x64 Wc tile (tf32 mma) into smem, then score
// those 128 rows. Scoring: 4 rows per warp-iter, 8 lanes per row (8 dims each).
// Negatives gathered from fp16 z copy (halves L2 gather bytes).
__global__ __launch_bounds__(256, 2)
void fused_kernel(const float* __restrict__ z,
                  const float* __restrict__ c,
                  const float* __restrict__ W,
                  const float* __restrict__ bias,
                  const int* __restrict__ batch_index,
                  const int* __restrict__ seq_index) {
    __shared__ __align__(16) char smem_u[128 * WCSTR * 4];   // 36864 B union
    __shared__ float s_loss, s_acc;

    float* sA  = (float*)smem_u;            // [128][36]
    float* sB  = sA + 128 * 36;             // [64][36]
    float* sWc = (float*)smem_u;            // [128][WCSTR] overlays sA/sB later

    const int bx = blockIdx.x;
    const int k  = bx % KSTEPS;             // k fastest -> c tile L2 reuse
    const int m0 = (bx / KSTEPS) * 128;

    const int tid  = threadIdx.x;
    const int warp = tid >> 5;
    const int lane = tid & 31;
    const int grp  = lane >> 2;             // 0..7 (mma)
    const int tig  = lane & 3;              // 0..3 (mma)
    const int mw   = warp * 16;

    if (tid == 0) { s_loss = 0.f; s_acc = 0.f; }

    // ---------------- GEMM phase (tf32 mma.sync) ----------------
    const int base = tid >> 3;              // 0..31 loader row
    const int c4   = tid & 7;               // 0..7  float4 col

    const float* aptr[4];
#pragma unroll
    for (int i = 0; i < 4; i++) {
        int m  = m0 + base + 32 * i;
        int su = m / LEN;
        int l  = m - su * LEN;
        aptr[i] = c + ((size_t)(su * T_ + l)) * CD + c4 * 4;
    }
    const float* bptr = W + (size_t)k * ZD * CD + c4 * 4;

    float acc[8][4];
#pragma unroll
    for (int j = 0; j < 8; j++)
#pragma unroll
        for (int i = 0; i < 4; i++) acc[j][i] = 0.f;

    for (int kk = 0; kk < CD; kk += 32) {
#pragma unroll
        for (int i = 0; i < 4; i++) {
            float4 v = *(const float4*)(aptr[i] + kk);
            float* d = &sA[(base + 32 * i) * 36 + c4 * 4];
            d[0] = f2tf32(v.x); d[1] = f2tf32(v.y);
            d[2] = f2tf32(v.z); d[3] = f2tf32(v.w);
        }
#pragma unroll
        for (int j = 0; j < 2; j++) {
            int nB   = base + 32 * j;
            float4 v = *(const float4*)(bptr + (size_t)nB * CD + kk);
            float* d = &sB[nB * 36 + c4 * 4];
            d[0] = f2tf32(v.x); d[1] = f2tf32(v.y);
            d[2] = f2tf32(v.z); d[3] = f2tf32(v.w);
        }
        __syncthreads();
#pragma unroll
        for (int ks = 0; ks < 4; ks++) {
            const int kc0 = ks * 8;
            const float* ar = &sA[(mw + grp) * 36 + kc0 + tig];
            unsigned a0 = __float_as_uint(ar[0]);
            unsigned a1 = __float_as_uint(ar[8 * 36]);
            unsigned a2 = __float_as_uint(ar[4]);
            unsigned a3 = __float_as_uint(ar[8 * 36 + 4]);
#pragma unroll
            for (int j = 0; j < 8; j++) {
                const float* br = &sB[(8 * j + grp) * 36 + kc0 + tig];
                unsigned b0 = __float_as_uint(br[0]);
                unsigned b1 = __float_as_uint(br[4]);
                asm volatile(
                    "mma.sync.aligned.m16n8k8.row.col.f32.tf32.tf32.f32 "
                    "{%0,%1,%2,%3}, {%4,%5,%6,%7}, {%8,%9}, {%0,%1,%2,%3};\n"
                    : "+f"(acc[j][0]), "+f"(acc[j][1]),
                      "+f"(acc[j][2]), "+f"(acc[j][3])
                    : "r"(a0), "r"(a1), "r"(a2), "r"(a3), "r"(b0), "r"(b1));
            }
        }
        __syncthreads();
    }

    // ---------------- epilogue: bias + park Wc tile in smem ----------------
#pragma unroll
    for (int j = 0; j < 8; j++) {
        const int n = 8 * j + 2 * tig;
        float2 bb = *(const float2*)(bias + k * ZD + n);
        float2 o0, o1;
        o0.x = acc[j][0] + bb.x; o0.y = acc[j][1] + bb.y;
        o1.x = acc[j][2] + bb.x; o1.y = acc[j][3] + bb.y;
        *(float2*)(sWc + (size_t)(mw + grp) * WCSTR + n)     = o0;
        *(float2*)(sWc + (size_t)(mw + grp + 8) * WCSTR + n) = o1;
    }
    __syncthreads();

    // ---------------- scoring phase: quad-parallel, 4 rows/warp-iter -------
    const int quad = lane >> 3;             // 0..3 : which row of the group
    const int lq   = lane & 7;              // 0..7 : lane within quad (8 dims each)

    float warp_loss = 0.f, warp_acc = 0.f;  // valid at quad leaders (lq==0)

#pragma unroll
    for (int it = 0; it < 4; it++) {
        const int r  = mw + it * 4 + quad;
        const int m  = m0 + r;
        const int su = m / LEN;
        const int l  = m - su * LEN;
        const int s  = su >> 3;
        const int u  = su & 7;

        // Wc fragment: 8 dims per lane
        const float4* w4 = (const float4*)(sWc + (size_t)r * WCSTR + lq * 8);
        float4 w0 = w4[0], w1 = w4[1];

        // positive z row (fp32 for accuracy; 1/18 of traffic)
        const float4* zp = (const float4*)(z +
            (size_t)(su * T_ + (l + k + 1)) * ZD + lq * 8);
        float4 z0 = zp[0], z1 = zp[1];

        float p[18];
        p[0] = dot8(z0, z1, w0, w1);

        // preload this quad's neg indices: lane lq holds n = lq, lq+8, lq+16
        const int* bi = batch_index + (k * U_ + u) * NEG;
        const int* si = seq_index + ((size_t)((k * S_ + s) * U_ + u) * NEG) * LEN + l;
        int bn_r[3], sn_r[3];
#pragma unroll
        for (int j = 0; j < 3; j++) {
            int n = lq + 8 * j;
            if (n < NEG) {
                bn_r[j] = __ldg(bi + n);
                sn_r[j] = __ldg(si + (size_t)n * LEN);
            } else { bn_r[j] = 0; sn_r[j] = 0; }
        }

#pragma unroll
        for (int n = 0; n < NEG; n++) {
            int bn = __shfl_sync(0xffffffffu, bn_r[n >> 3], n & 7, 8);
            int sn = __shfl_sync(0xffffffffu, sn_r[n >> 3], n & 7, 8);
            // fp16 gather: 8 dims = 16 bytes = one LDG.128 per lane
            const uint4* zn = (const uint4*)((const __half*)g_zh +
                (size_t)((s * U_ + bn) * T_ + (k + 1 + sn)) * ZD + lq * 8);
            uint4 raw = *zn;
            __half2 h0 = *(__half2*)&raw.x;
            __half2 h1 = *(__half2*)&raw.y;
            __half2 h2 = *(__half2*)&raw.z;
            __half2 h3 = *(__half2*)&raw.w;
            float2 a0 = __half22float2(h0);
            float2 a1 = __half22float2(h1);
            float2 a2 = __half22float2(h2);
            float2 a3 = __half22float2(h3);
            float sum = a0.x * w0.x;
            sum = fmaf(a0.y, w0.y, sum);
            sum = fmaf(a1.x, w0.z, sum);
            sum = fmaf(a1.y, w0.w, sum);
            sum = fmaf(a2.x, w1.x, sum);
            sum = fmaf(a2.y, w1.y, sum);
            sum = fmaf(a3.x, w1.z, sum);
            sum = fmaf(a3.y, w1.w, sum);
            p[1 + n] = sum;
        }

        // 3-round butterfly within each quad
#pragma unroll
        for (int off = 4; off >= 1; off >>= 1) {
#pragma unroll
            for (int n = 0; n < 18; n++)
                p[n] += __shfl_xor_sync(0xffffffffu, p[n], off);
        }

        if (lq == 0) {     // 4 quad leaders execute these instructions together
            float f0 = p[0] * 0.125f;
            float mxn = p[1];
#pragma unroll
            for (int n = 2; n < 18; n++) mxn = fmaxf(mxn, p[n]);
            mxn *= 0.125f;
            float mx = fmaxf(f0, mxn);
            float se = __expf(f0 - mx);
#pragma unroll
            for (int n = 1; n < 18; n++) se += __expf(p[n] * 0.125f - mx);
            warp_loss += (mx + __logf(se)) - f0;
            warp_acc  += (f0 >= mxn) ? 1.f : 0.f;   // argmax==0 (ties -> 0)
        }
    }

    // combine the 4 quad leaders (lanes 0,8,16,24)
    warp_loss += __shfl_xor_sync(0xffffffffu, warp_loss, 8);
    warp_loss += __shfl_xor_sync(0xffffffffu, warp_loss, 16);
    warp_acc  += __shfl_xor_sync(0xffffffffu, warp_acc, 8);
    warp_acc  += __shfl_xor_sync(0xffffffffu, warp_acc, 16);

    if (lane == 0) {
        atomicAdd(&s_loss, warp_loss);
        atomicAdd(&s_acc, warp_acc);
    }
    __syncthreads();
    if (tid == 0) {
        atomicAdd(&g_loss_sum[k], s_loss);
        atomicAdd(&g_acc_sum[k], s_acc);
    }
}

// -------------------------------------------------------------------------
__global__ void finalize_kernel(float* __restrict__ out, int out_size) {
    __shared__ float sl[KSTEPS];
    int t = threadIdx.x;
    const float inv = 1.f / (float)(SU * LEN);
    if (t < KSTEPS) {
        sl[t] = g_loss_sum[t] * inv;
        if (1 + t < out_size) out[1 + t] = g_acc_sum[t] * inv;
    }
    __syncthreads();
    if (t == 0 && out_size > 0) {
        float sum = 0.f;
        for (int i = 0; i < KSTEPS; i++) sum += sl[i];
        out[0] = sum * (1.f / (float)KSTEPS);
    }
    for (int i = 13 + t; i < out_size; i += blockDim.x) out[i] = 0.f;
}

// -------------------------------------------------------------------------
extern "C" void kernel_launch(void* const* d_in, const int* in_sizes, int n_in,
                              void* d_out, int out_size) {
    const float* z           = (const float*)d_in[0];
    const float* c           = (const float*)d_in[1];
    const float* W           = (const float*)d_in[2];
    const float* b           = (const float*)d_in[3];
    const int*   batch_index = (const int*)d_in[4];
    const int*   seq_index   = (const int*)d_in[5];

    zero_sums_kernel<<<1, 32>>>();

    const size_t n4 = (size_t)SU * T_ * ZD / 4;
    convert_z_kernel<<<(unsigned)((n4 + 255) / 256), 256>>>(z);

    fused_kernel<<<NTILES * KSTEPS, 256>>>(z, c, W, b, batch_index, seq_index);
    finalize_kernel<<<1, 64>>>((float*)d_out, out_size);
}

// round 11
// speedup vs baseline: 3.8644x; 1.3488x over previous
#include <cuda_runtime.h>
#include <cuda_fp16.h>
#include <math.h>

// Problem constants
#define S_      8
#define U_      8
#define KSTEPS  12
#define NEG     17
#define ZD      64
#define CD      256
#define T_      1140
#define LEN     1128
#define SU      64              // S_*U_
#define MROWS   (SU*LEN)        // 72192
#define NTILES  (MROWS/128)     // 564
#define WCSTR   72              // smem Wc row stride (floats)
#define CK      64              // K-chunk (fp16 GEMM)
#define SAS     72              // smem A/B row stride in halves (144B: ldmatrix conflict-free)

__device__ float g_loss_sum[KSTEPS];
__device__ float g_acc_sum[KSTEPS];
__device__ __half g_zh[(size_t)SU * T_ * ZD];   // fp16 copy of z (9.3 MB)

// -------------------------------------------------------------------------
__global__ void zero_sums_kernel() {
    int t = threadIdx.x;
    if (t < KSTEPS) { g_loss_sum[t] = 0.f; g_acc_sum[t] = 0.f; }
}

// z -> fp16 (once per launch; deterministic)
__global__ void convert_z_kernel(const float* __restrict__ z) {
    size_t i = (size_t)blockIdx.x * blockDim.x + threadIdx.x;   // one float4
    const size_t n4 = (size_t)SU * T_ * ZD / 4;
    if (i < n4) {
        float4 v = ((const float4*)z)[i];
        __half2 h0 = __floats2half2_rn(v.x, v.y);
        __half2 h1 = __floats2half2_rn(v.z, v.w);
        uint2 o;
        o.x = *(unsigned*)&h0;
        o.y = *(unsigned*)&h1;
        ((uint2*)g_zh)[i] = o;
    }
}

// -------------------------------------------------------------------------
__device__ __forceinline__ uint2 pack_h4(float4 v) {
    __half2 h0 = __floats2half2_rn(v.x, v.y);
    __half2 h1 = __floats2half2_rn(v.z, v.w);
    uint2 o;
    o.x = *(unsigned*)&h0;
    o.y = *(unsigned*)&h1;
    return o;
}

__device__ __forceinline__ void ldmx4(unsigned* r, unsigned addr) {
    asm volatile("ldmatrix.sync.aligned.m8n8.x4.shared.b16 {%0,%1,%2,%3}, [%4];"
                 : "=r"(r[0]), "=r"(r[1]), "=r"(r[2]), "=r"(r[3]) : "r"(addr));
}

__device__ __forceinline__ void mma16816(float* c, const unsigned* a,
                                         unsigned b0, unsigned b1) {
    asm volatile(
        "mma.sync.aligned.m16n8k16.row.col.f32.f16.f16.f32 "
        "{%0,%1,%2,%3}, {%4,%5,%6,%7}, {%8,%9}, {%0,%1,%2,%3};\n"
        : "+f"(c[0]), "+f"(c[1]), "+f"(c[2]), "+f"(c[3])
        : "r"(a[0]), "r"(a[1]), "r"(a[2]), "r"(a[3]), "r"(b0), "r"(b1));
}

// -------------------------------------------------------------------------
// Fused: per CTA compute one 128x64 Wc tile via fp16 mma (ldmatrix fragments)
// into smem, then score those 128 rows (quad-parallel, fp16 neg gathers).
__global__ __launch_bounds__(256, 2)
void fused_kernel(const float* __restrict__ z,
                  const float* __restrict__ c,
                  const float* __restrict__ W,
                  const float* __restrict__ bias,
                  const int* __restrict__ batch_index,
                  const int* __restrict__ seq_index) {
    __shared__ __align__(16) char smem_u[128 * WCSTR * 4];   // 36864 B union
    __shared__ float s_loss, s_acc;

    __half* sA  = (__half*)smem_u;          // [128][SAS] = 18432 B
    __half* sB  = sA + 128 * SAS;           // [64][SAS]  =  9216 B
    float*  sWc = (float*)smem_u;           // [128][WCSTR] overlays later

    const int bx = blockIdx.x;
    const int k  = bx % KSTEPS;             // k fastest -> c tile L2 reuse
    const int m0 = (bx / KSTEPS) * 128;

    const int tid  = threadIdx.x;
    const int warp = tid >> 5;
    const int lane = tid & 31;
    const int grp  = lane >> 2;             // 0..7 (mma C rows)
    const int tig  = lane & 3;              // 0..3
    const int mw   = warp * 16;

    if (tid == 0) { s_loss = 0.f; s_acc = 0.f; }

    // ---------------- GEMM phase (fp16 ldmatrix + mma.m16n8k16) ------------
    const int lr  = tid >> 4;               // 0..15 loader row-in-pass
    const int c16 = tid & 15;               // float4 col within 64-wide chunk

    const float* arow[8];
#pragma unroll
    for (int p = 0; p < 8; p++) {
        int m  = m0 + lr + 16 * p;
        int su = m / LEN;
        int l  = m - su * LEN;
        arow[p] = c + ((size_t)(su * T_ + l)) * CD + c16 * 4;
    }
    const float* brow = W + (size_t)k * ZD * CD + c16 * 4;

    // ldmatrix lane address offsets (halves): rows lane&15, col +8 for lanes>=16
    const unsigned sA_b = (unsigned)__cvta_generic_to_shared(sA);
    const unsigned sB_b = (unsigned)__cvta_generic_to_shared(sB);
    const unsigned laneA = sA_b + (((mw + (lane & 15)) * SAS + ((lane >> 4) << 3)) << 1);
    const unsigned laneB = sB_b + ((((lane & 15)) * SAS + ((lane >> 4) << 3)) << 1);

    float acc[8][4];
#pragma unroll
    for (int j = 0; j < 8; j++)
#pragma unroll
        for (int i = 0; i < 4; i++) acc[j][i] = 0.f;

    for (int kk = 0; kk < CD; kk += CK) {
        // A: 128 rows x 64 cols -> fp16 smem (8 passes of 16 rows)
#pragma unroll
        for (int p = 0; p < 8; p++) {
            float4 v = *(const float4*)(arow[p] + kk);
            *(uint2*)&sA[(lr + 16 * p) * SAS + c16 * 4] = pack_h4(v);
        }
        // B: 64 rows x 64 cols (4 passes of 16 rows)
#pragma unroll
        for (int p = 0; p < 4; p++) {
            int n = lr + 16 * p;
            float4 v = *(const float4*)(brow + (size_t)n * CD + kk);
            *(uint2*)&sB[n * SAS + c16 * 4] = pack_h4(v);
        }
        __syncthreads();

#pragma unroll
        for (int ks = 0; ks < 4; ks++) {        // k-steps of 16 within chunk
            unsigned a[4];
            ldmx4(a, laneA + (ks << 5));        // +16*ks halves = 32*ks bytes
#pragma unroll
            for (int j2 = 0; j2 < 4; j2++) {    // n-pairs of 16
                unsigned bf[4];
                ldmx4(bf, laneB + (unsigned)(j2 * 16 * SAS * 2) + (ks << 5));
                mma16816(acc[2 * j2],     a, bf[0], bf[2]);
                mma16816(acc[2 * j2 + 1], a, bf[1], bf[3]);
            }
        }
        __syncthreads();
    }

    // ---------------- epilogue: bias + park Wc tile in smem ----------------
#pragma unroll
    for (int j = 0; j < 8; j++) {
        const int n = 8 * j + 2 * tig;
        float2 bb = *(const float2*)(bias + k * ZD + n);
        float2 o0, o1;
        o0.x = acc[j][0] + bb.x; o0.y = acc[j][1] + bb.y;
        o1.x = acc[j][2] + bb.x; o1.y = acc[j][3] + bb.y;
        *(float2*)(sWc + (size_t)(mw + grp) * WCSTR + n)     = o0;
        *(float2*)(sWc + (size_t)(mw + grp + 8) * WCSTR + n) = o1;
    }
    __syncthreads();

    // ---------------- scoring phase: quad-parallel, 4 rows/warp-iter -------
    const int quad = lane >> 3;             // 0..3 : which row of the group
    const int lq   = lane & 7;              // 0..7 : lane within quad (8 dims)

    float warp_loss = 0.f, warp_acc = 0.f;  // valid at quad leaders (lq==0)

#pragma unroll
    for (int it = 0; it < 4; it++) {
        const int r  = mw + it * 4 + quad;
        const int m  = m0 + r;
        const int su = m / LEN;
        const int l  = m - su * LEN;
        const int s  = su >> 3;
        const int u  = su & 7;

        const float4* w4 = (const float4*)(sWc + (size_t)r * WCSTR + lq * 8);
        float4 w0 = w4[0], w1 = w4[1];

        const float4* zp = (const float4*)(z +
            (size_t)(su * T_ + (l + k + 1)) * ZD + lq * 8);
        float4 z0 = zp[0], z1 = zp[1];

        float p[18];
        {
            float sum = z0.x * w0.x;
            sum = fmaf(z0.y, w0.y, sum);
            sum = fmaf(z0.z, w0.z, sum);
            sum = fmaf(z0.w, w0.w, sum);
            sum = fmaf(z1.x, w1.x, sum);
            sum = fmaf(z1.y, w1.y, sum);
            sum = fmaf(z1.z, w1.z, sum);
            sum = fmaf(z1.w, w1.w, sum);
            p[0] = sum;
        }

        const int* bi = batch_index + (k * U_ + u) * NEG;
        const int* si = seq_index + ((size_t)((k * S_ + s) * U_ + u) * NEG) * LEN + l;
        int bn_r[3], sn_r[3];
#pragma unroll
        for (int j = 0; j < 3; j++) {
            int n = lq + 8 * j;
            if (n < NEG) {
                bn_r[j] = __ldg(bi + n);
                sn_r[j] = __ldg(si + (size_t)n * LEN);
            } else { bn_r[j] = 0; sn_r[j] = 0; }
        }

#pragma unroll
        for (int n = 0; n < NEG; n++) {
            int bn = __shfl_sync(0xffffffffu, bn_r[n >> 3], n & 7, 8);
            int sn = __shfl_sync(0xffffffffu, sn_r[n >> 3], n & 7, 8);
            const uint4* zn = (const uint4*)((const __half*)g_zh +
                (size_t)((s * U_ + bn) * T_ + (k + 1 + sn)) * ZD + lq * 8);
            uint4 raw = *zn;
            __half2 h0 = *(__half2*)&raw.x;
            __half2 h1 = *(__half2*)&raw.y;
            __half2 h2 = *(__half2*)&raw.z;
            __half2 h3 = *(__half2*)&raw.w;
            float2 a0 = __half22float2(h0);
            float2 a1 = __half22float2(h1);
            float2 a2 = __half22float2(h2);
            float2 a3 = __half22float2(h3);
            float sum = a0.x * w0.x;
            sum = fmaf(a0.y, w0.y, sum);
            sum = fmaf(a1.x, w0.z, sum);
            sum = fmaf(a1.y, w0.w, sum);
            sum = fmaf(a2.x, w1.x, sum);
            sum = fmaf(a2.y, w1.y, sum);
            sum = fmaf(a3.x, w1.z, sum);
            sum = fmaf(a3.y, w1.w, sum);
            p[1 + n] = sum;
        }

        // 3-round butterfly within each quad
#pragma unroll
        for (int off = 4; off >= 1; off >>= 1) {
#pragma unroll
            for (int n = 0; n < 18; n++)
                p[n] += __shfl_xor_sync(0xffffffffu, p[n], off);
        }

        if (lq == 0) {     // 4 quad leaders execute together
            float f0 = p[0] * 0.125f;
            float mxn = p[1];
#pragma unroll
            for (int n = 2; n < 18; n++) mxn = fmaxf(mxn, p[n]);
            mxn *= 0.125f;
            float mx = fmaxf(f0, mxn);
            float se = __expf(f0 - mx);
#pragma unroll
            for (int n = 1; n < 18; n++) se += __expf(p[n] * 0.125f - mx);
            warp_loss += (mx + __logf(se)) - f0;
            warp_acc  += (f0 >= mxn) ? 1.f : 0.f;   // argmax==0 (ties -> 0)
        }
    }

    warp_loss += __shfl_xor_sync(0xffffffffu, warp_loss, 8);
    warp_loss += __shfl_xor_sync(0xffffffffu, warp_loss, 16);
    warp_acc  += __shfl_xor_sync(0xffffffffu, warp_acc, 8);
    warp_acc  += __shfl_xor_sync(0xffffffffu, warp_acc, 16);

    if (lane == 0) {
        atomicAdd(&s_loss, warp_loss);
        atomicAdd(&s_acc, warp_acc);
    }
    __syncthreads();
    if (tid == 0) {
        atomicAdd(&g_loss_sum[k], s_loss);
        atomicAdd(&g_acc_sum[k], s_acc);
    }
}

// -------------------------------------------------------------------------
__global__ void finalize_kernel(float* __restrict__ out, int out_size) {
    __shared__ float sl[KSTEPS];
    int t = threadIdx.x;
    const float inv = 1.f / (float)(SU * LEN);
    if (t < KSTEPS) {
        sl[t] = g_loss_sum[t] * inv;
        if (1 + t < out_size) out[1 + t] = g_acc_sum[t] * inv;
    }
    __syncthreads();
    if (t == 0 && out_size > 0) {
        float sum = 0.f;
        for (int i = 0; i < KSTEPS; i++) sum += sl[i];
        out[0] = sum * (1.f / (float)KSTEPS);
    }
    for (int i = 13 + t; i < out_size; i += blockDim.x) out[i] = 0.f;
}

// -------------------------------------------------------------------------
extern "C" void kernel_launch(void* const* d_in, const int* in_sizes, int n_in,
                              void* d_out, int out_size) {
    const float* z           = (const float*)d_in[0];
    const float* c           = (const float*)d_in[1];
    const float* W           = (const float*)d_in[2];
    const float* b           = (const float*)d_in[3];
    const int*   batch_index = (const int*)d_in[4];
    const int*   seq_index   = (const int*)d_in[5];

    zero_sums_kernel<<<1, 32>>>();

    const size_t n4 = (size_t)SU * T_ * ZD / 4;
    convert_z_kernel<<<(unsigned)((n4 + 255) / 256), 256>>>(z);

    fused_kernel<<<NTILES * KSTEPS, 256>>>(z, c, W, b, batch_index, seq_index);
    finalize_kernel<<<1, 64>>>((float*)d_out, out_size);
}